// round 15
// baseline (speedup 1.0000x reference)
#include <cuda_runtime.h>
#include <cuda_fp16.h>

// SwinV2 shifted-window attention, B=16, H=W=64, C=256, heads=8, hd=32.
// Round 15: round-14 GEMMs unchanged; attention gets (a) launch_bounds
// (128,6) -> 6 blocks/SM (was reg-capped at 5), (b) cp.async staging of
// the K hi/lo planes overlapped with the V byte_perm transpose, bias and
// Q fragment loads. Arithmetic identical to round 14.

#define NWIN   1024
#define NTOK   64
#define CDIM   256
#define NHEAD  8
#define HD     32

// -------- scratch (device globals; no allocation) --------
__device__ unsigned       g_qh [NWIN * NHEAD * NTOK * 16];
__device__ unsigned       g_ql [NWIN * NHEAD * NTOK * 16];
__device__ unsigned       g_kh [NWIN * NHEAD * NTOK * 16];
__device__ unsigned       g_kl [NWIN * NHEAD * NTOK * 16];
__device__ unsigned       g_v16[NWIN * NHEAD * NTOK * 16];
__device__ unsigned short g_ao [NWIN * NTOK * CDIM];
__device__ unsigned short g_xh [16 * 64 * 64 * CDIM];
__device__ unsigned short g_wh [4 * CDIM * CDIM];
__device__ float          g_bias16[NHEAD * 225];
__device__ float          g_scale[NHEAD];

// -------- helpers --------
__device__ __forceinline__ unsigned pkh(float lo, float hi) {
    unsigned r;
    asm("cvt.rn.f16x2.f32 %0, %1, %2;" : "=r"(r) : "f"(hi), "f"(lo));
    return r;
}
__device__ __forceinline__ void mma16(float* c, const unsigned* a, const unsigned* b) {
    asm volatile("mma.sync.aligned.m16n8k16.row.col.f32.f16.f16.f32 "
                 "{%0,%1,%2,%3},{%4,%5,%6,%7},{%8,%9},{%0,%1,%2,%3};"
                 : "+f"(c[0]), "+f"(c[1]), "+f"(c[2]), "+f"(c[3])
                 : "r"(a[0]), "r"(a[1]), "r"(a[2]), "r"(a[3]),
                   "r"(b[0]), "r"(b[1]));
}
__device__ __forceinline__ void ldsm4(unsigned* r, unsigned addr) {
    asm volatile("ldmatrix.sync.aligned.m8n8.x4.shared.b16 {%0,%1,%2,%3}, [%4];"
                 : "=r"(r[0]), "=r"(r[1]), "=r"(r[2]), "=r"(r[3]) : "r"(addr));
}
__device__ __forceinline__ void cp16(unsigned dst, const void* src) {
    asm volatile("cp.async.cg.shared.global [%0], [%1], 16;" :: "r"(dst), "l"(src));
}
__device__ __forceinline__ void cp_commit() {
    asm volatile("cp.async.commit_group;");
}
template<int N> __device__ __forceinline__ void cp_wait() {
    asm volatile("cp.async.wait_group %0;" :: "n"(N));
}

// -------- halved-tile GEMM smem geometry: 3 resident stages, 2 CTAs/SM ----
#define HA_BYTES  (128 * 144)
#define HSTG      (2 * HA_BYTES)
#define H_ROWB    0
#define H_BIAS    512
#define H_BUF     2048
#define H_SMEM    (H_BUF + 3 * HSTG)

// ============================================================
// Kernel 0: continuous-position-bias MLP
// ============================================================
__global__ void swin_bias_kernel(const float* __restrict__ ls,
                                 const float* __restrict__ w1,
                                 const float* __restrict__ b1,
                                 const float* __restrict__ w2)
{
    __shared__ float part[16][8];
    const int t   = blockIdx.x;
    const int i   = t / 15;
    const int j   = t % 15;
    const int tid = threadIdx.x;
    const int warp = tid >> 5;
    const int lane = tid & 31;

    float rh = (float)(i - 7) * (8.0f / 7.0f);
    float rw = (float)(j - 7) * (8.0f / 7.0f);
    rh = copysignf(log2f(fabsf(rh) + 1.0f) * (1.0f / 3.0f), rh);
    rw = copysignf(log2f(fabsf(rw) + 1.0f) * (1.0f / 3.0f), rw);

    float hv = fmaxf(0.0f, rh * w1[tid] + rw * w1[512 + tid] + b1[tid]);

    float p[8];
#pragma unroll
    for (int h = 0; h < 8; ++h) p[h] = hv * w2[tid * 8 + h];
#pragma unroll
    for (int off = 16; off; off >>= 1)
#pragma unroll
        for (int h = 0; h < 8; ++h) p[h] += __shfl_xor_sync(0xffffffffu, p[h], off);
    if (lane == 0)
#pragma unroll
        for (int h = 0; h < 8; ++h) part[warp][h] = p[h];
    __syncthreads();

    if (tid < 8) {
        float s = 0.0f;
#pragma unroll
        for (int g = 0; g < 16; ++g) s += part[g][tid];
        g_bias16[tid * 225 + t] = 16.0f / (1.0f + expf(-s));
    }
    if (blockIdx.x == 0 && tid < 8)
        g_scale[tid] = expf(fminf(ls[tid], 4.6051701860f));
}

// ============================================================
// Kernel 0b: x -> fp16; W -> transposed fp16 [n][k]
// ============================================================
__global__ void swin_cvt_kernel(const float* __restrict__ x,
                                const float* __restrict__ Wq,
                                const float* __restrict__ Wk,
                                const float* __restrict__ Wv,
                                const float* __restrict__ Wo)
{
    const int blk = blockIdx.x;
    const int tid = threadIdx.x;
    if (blk < 16384) {
        int i4 = blk * 256 + tid;
        float4 v = ((const float4*)x)[i4];
        ((uint2*)g_xh)[i4] = make_uint2(pkh(v.x, v.y), pkh(v.z, v.w));
    } else {
        int r = blk - 16384;
        int m = r >> 6;
        const float* W = (m == 0) ? Wq : (m == 1) ? Wk : (m == 2) ? Wv : Wo;
        int idx = (r & 63) * 256 + tid;
        int n  = idx >> 6;
        int k4 = (idx & 63) * 4;
        float a0 = W[(k4 + 0) * 256 + n];
        float a1 = W[(k4 + 1) * 256 + n];
        float a2 = W[(k4 + 2) * 256 + n];
        float a3 = W[(k4 + 3) * 256 + n];
        ((uint2*)(g_wh + m * 65536))[idx] = make_uint2(pkh(a0, a1), pkh(a2, a3));
    }
}

// ============================================================
// Kernel 1: QKV. grid (1024, 3): x = bw*2+nh, y = 0:Q,1:K,2:V.
// CTA: M=128 x N=128, 16 warps (M32xN32), 3-stage cp.async, 2 CTAs/SM.
// ============================================================
__global__ void __launch_bounds__(512, 2)
swin_qkv_kernel(const float* __restrict__ bq,
                const float* __restrict__ bk,
                const float* __restrict__ bv)
{
    extern __shared__ char smem[];
    const unsigned sb = (unsigned)__cvta_generic_to_shared(smem);
    unsigned* rowb_s = (unsigned*)(smem + H_ROWB);
    float*    bias_s = (float*)(smem + H_BIAS);

    const int bx   = blockIdx.x;
    const int bw   = bx >> 1;
    const int nh   = bx & 1;
    const int m    = blockIdx.y;
    const int tid  = threadIdx.x;
    const int warp = tid >> 5;
    const int lane = tid & 31;
    const int g    = lane >> 2;
    const int t    = lane & 3;
    const int mw   = warp >> 2;
    const int nq   = warp & 3;

    const unsigned alm = lane & 15;
    const unsigned alk = (lane >> 4) << 4;
    const unsigned blm = (lane & 7) + ((lane >> 4) << 3);
    const unsigned blk = ((lane >> 3) & 1) << 4;

    if (tid < 128) {
        int wv = bw * 2 + (tid >> 6);
        int b = wv >> 6, wy = (wv >> 3) & 7, wx = wv & 7;
        int tok = tid & 63;
        int sy = ((wy << 3) + (tok >> 3) + 4) & 63;
        int sx = ((wx << 3) + (tok & 7) + 4) & 63;
        rowb_s[tid] = ((((b << 6) | sy) << 6) | sx) << 8;
    }
    if (tid < 128) {
        const float* bp = (m == 0) ? bq : (m == 1) ? bk : bv;
        bias_s[tid] = bp[nh * 128 + tid];
    }
    __syncthreads();

    const int srow = tid >> 3;
    const int sjj  = tid & 7;
    const unsigned rb0 = rowb_s[srow];
    const unsigned rb1 = rowb_s[srow + 64];
    const unsigned sto0 = srow * 144 + sjj * 16;
    const unsigned sto1 = (srow + 64) * 144 + sjj * 16;
    const unsigned short* wh = g_wh + m * 65536 + (nh << 15);

#define STAGE(c_, st_) do {                                                    \
        unsigned _a = sb + H_BUF + (st_) * HSTG;                               \
        cp16(_a + sto0, g_xh + rb0 + (c_) * 64 + sjj * 8);                     \
        cp16(_a + sto1, g_xh + rb1 + (c_) * 64 + sjj * 8);                     \
        unsigned _bB = _a + HA_BYTES;                                          \
        cp16(_bB + sto0, wh + srow * 256 + (c_) * 64 + sjj * 8);               \
        cp16(_bB + sto1, wh + (srow + 64) * 256 + (c_) * 64 + sjj * 8);        \
        cp_commit();                                                           \
    } while (0)

    STAGE(0, 0); STAGE(1, 1); STAGE(2, 2);

    float acc[2][4][4];
#pragma unroll
    for (int mt = 0; mt < 2; ++mt)
#pragma unroll
        for (int nt = 0; nt < 4; ++nt)
#pragma unroll
            for (int q = 0; q < 4; ++q) acc[mt][nt][q] = 0.0f;

#pragma unroll 1
    for (int c = 0; c < 4; ++c) {
        if      (c == 0) cp_wait<2>();
        else if (c == 1) cp_wait<1>();
        else if (c == 2) cp_wait<1>();
        else             cp_wait<0>();
        __syncthreads();
        if (c == 1) STAGE(3, 0);

        const unsigned sbX = sb + H_BUF + (c % 3) * HSTG;
        const unsigned sbB = sbX + HA_BYTES;
#pragma unroll
        for (int ks = 0; ks < 4; ++ks) {
            unsigned a[2][4];
            ldsm4(a[0], sbX + (mw * 32 + alm) * 144 + ks * 32 + alk);
            ldsm4(a[1], sbX + (mw * 32 + 16 + alm) * 144 + ks * 32 + alk);
#pragma unroll
            for (int ntp = 0; ntp < 2; ++ntp) {
                unsigned b4[4];
                ldsm4(b4, sbB + (nq * 32 + ntp * 16 + blm) * 144 + ks * 32 + blk);
                mma16(acc[0][2 * ntp],     a[0], b4);
                mma16(acc[0][2 * ntp + 1], a[0], b4 + 2);
                mma16(acc[1][2 * ntp],     a[1], b4);
                mma16(acc[1][2 * ntp + 1], a[1], b4 + 2);
            }
        }
    }
#undef STAGE

    const int head = nh * 4 + nq;
    float2 bb[4];
#pragma unroll
    for (int nt = 0; nt < 4; ++nt)
        bb[nt] = *(float2*)(bias_s + nq * 32 + nt * 8 + 2 * t);
#pragma unroll
    for (int mt = 0; mt < 2; ++mt)
#pragma unroll
        for (int nt = 0; nt < 4; ++nt) {
            acc[mt][nt][0] += bb[nt].x;  acc[mt][nt][1] += bb[nt].y;
            acc[mt][nt][2] += bb[nt].x;  acc[mt][nt][3] += bb[nt].y;
        }

    if (m < 2) {
#pragma unroll
        for (int mt = 0; mt < 2; ++mt)
#pragma unroll
            for (int rh = 0; rh < 2; ++rh) {
                float s = 0.0f;
#pragma unroll
                for (int nt = 0; nt < 4; ++nt)
                    s += acc[mt][nt][rh * 2]     * acc[mt][nt][rh * 2]
                       + acc[mt][nt][rh * 2 + 1] * acc[mt][nt][rh * 2 + 1];
                s += __shfl_xor_sync(0xffffffffu, s, 1);
                s += __shfl_xor_sync(0xffffffffu, s, 2);
                float inv = 1.0f / fmaxf(sqrtf(s), 1e-12f);
#pragma unroll
                for (int nt = 0; nt < 4; ++nt) {
                    acc[mt][nt][rh * 2]     *= inv;
                    acc[mt][nt][rh * 2 + 1] *= inv;
                }
            }
    }

#pragma unroll
    for (int mt = 0; mt < 2; ++mt)
#pragma unroll
        for (int rh = 0; rh < 2; ++rh)
#pragma unroll
            for (int nt = 0; nt < 4; ++nt) {
                int n    = mw * 32 + mt * 16 + rh * 8 + g;
                int win  = bw * 2 + (n >> 6);
                int tok  = n & 63;
                int d    = nt * 8 + 2 * t;
                int idx  = (((win << 3) | head) << 10) + (tok << 4) + (d >> 1);
                float vx = acc[mt][nt][rh * 2];
                float vy = acc[mt][nt][rh * 2 + 1];
                if (m == 2) {
                    g_v16[idx] = pkh(vx, vy);
                } else {
                    unsigned hw = pkh(vx, vy);
                    float2 hf = __half22float2(*(__half2*)&hw);
                    unsigned lw = pkh(vx - hf.x, vy - hf.y);
                    if (m == 0) { g_qh[idx] = hw; g_ql[idx] = lw; }
                    else        { g_kh[idx] = hw; g_kl[idx] = lw; }
                }
            }
}

// ============================================================
// Kernel 2: fully-fp16 MMA attention. grid (1024, 8), 128 threads.
// cp.async K staging overlapped with V transpose / bias / Q loads;
// launch_bounds(128,6) for 6 blocks/SM.
// ============================================================
__global__ void __launch_bounds__(128, 6)
swin_attn_kernel()
{
    __shared__ __align__(16) unsigned khs[64 * 20];
    __shared__ __align__(16) unsigned kls[64 * 20];
    __shared__ __align__(16) unsigned vts[32 * 36];
    __shared__ __align__(16) unsigned ps[4][16 * 36];
    __shared__ float bs[228];

    const int w    = blockIdx.x;
    const int h    = blockIdx.y;
    const int tid  = threadIdx.x;
    const int wt   = tid >> 5;
    const int lane = tid & 31;
    const int g    = lane >> 2;
    const int t    = lane & 3;
    const int pbase = ((w << 3) | h) << 10;

    const unsigned alm = lane & 15;
    const unsigned alk = (lane >> 4) << 4;
    const unsigned blm = (lane & 7) + ((lane >> 4) << 3);
    const unsigned blk = ((lane >> 3) & 1) << 4;

    const unsigned khs_b = (unsigned)__cvta_generic_to_shared(khs);
    const unsigned kls_b = (unsigned)__cvta_generic_to_shared(kls);

    // ---- stage K hi/lo via cp.async (in flight during V/bias/Q work) ----
#pragma unroll
    for (int it = 0; it < 2; ++it) {
        int i4  = tid + it * 128;          // 0..255 uint4 chunks
        int row = i4 >> 2;
        int c4  = (i4 & 3) << 2;
        unsigned off = (row * 20 + c4) << 2;
        cp16(khs_b + off, g_kh + pbase + i4 * 4);
        cp16(kls_b + off, g_kl + pbase + i4 * 4);
    }
    cp_commit();

    // ---- stage V^T (byte_perm) while K copies fly ----
    {
        const int mp = tid & 31;
        const int dp = tid >> 5;
        const uint4* v4 = (const uint4*)(g_v16 + pbase);
        uint4 a = v4[(2 * mp) * 4 + dp];
        uint4 b = v4[(2 * mp + 1) * 4 + dp];
        int d0 = dp * 8;
        vts[(d0 + 0) * 36 + mp] = __byte_perm(a.x, b.x, 0x5410);
        vts[(d0 + 1) * 36 + mp] = __byte_perm(a.x, b.x, 0x7632);
        vts[(d0 + 2) * 36 + mp] = __byte_perm(a.y, b.y, 0x5410);
        vts[(d0 + 3) * 36 + mp] = __byte_perm(a.y, b.y, 0x7632);
        vts[(d0 + 4) * 36 + mp] = __byte_perm(a.z, b.z, 0x5410);
        vts[(d0 + 5) * 36 + mp] = __byte_perm(a.z, b.z, 0x7632);
        vts[(d0 + 6) * 36 + mp] = __byte_perm(a.w, b.w, 0x5410);
        vts[(d0 + 7) * 36 + mp] = __byte_perm(a.w, b.w, 0x7632);
    }
    for (int i = tid; i < 225; i += 128) bs[i] = g_bias16[h * 225 + i];

    const float sc = g_scale[h];
    const int wy = (w >> 3) & 7, wx = w & 7;
    const bool mhb = (wy == 7), mwb = (wx == 7);
    const int r0 = wt * 16 + g;
    const int r1 = r0 + 8;

    // ---- Q fragments (overlap with K cp.async) ----
    const unsigned* qhp = g_qh + pbase;
    const unsigned* qlp = g_ql + pbase;
    unsigned aqh[2][4], aql[2][4];
#pragma unroll
    for (int ks = 0; ks < 2; ++ks) {
        int bidx = r0 * 16 + ks * 8 + t;
        aqh[ks][0] = qhp[bidx];        aqh[ks][1] = qhp[bidx + 128];
        aqh[ks][2] = qhp[bidx + 4];    aqh[ks][3] = qhp[bidx + 132];
        aql[ks][0] = qlp[bidx];        aql[ks][1] = qlp[bidx + 128];
        aql[ks][2] = qlp[bidx + 4];    aql[ks][3] = qlp[bidx + 132];
    }

    cp_wait<0>();
    __syncthreads();

    // ---- QK^T (fp16 hi/lo 3-term) ----
    float cc[8][4];
#pragma unroll
    for (int nt = 0; nt < 8; ++nt)
#pragma unroll
        for (int q = 0; q < 4; ++q) cc[nt][q] = 0.0f;

#pragma unroll
    for (int ks = 0; ks < 2; ++ks) {
#pragma unroll
        for (int ntp = 0; ntp < 4; ++ntp) {
            unsigned off = (ntp * 16 + blm) * 80 + ks * 32 + blk;
            unsigned rh4[4], rl4[4];
            ldsm4(rh4, khs_b + off);
            ldsm4(rl4, kls_b + off);
            mma16(cc[2 * ntp],     aqh[ks], rh4);
            mma16(cc[2 * ntp],     aql[ks], rh4);
            mma16(cc[2 * ntp],     aqh[ks], rl4);
            mma16(cc[2 * ntp + 1], aqh[ks], rh4 + 2);
            mma16(cc[2 * ntp + 1], aql[ks], rh4 + 2);
            mma16(cc[2 * ntp + 1], aqh[ks], rl4 + 2);
        }
    }

    const int ty0 = r0 >> 3, tx0 = r0 & 7;
    const int ty1 = r1 >> 3, tx1 = r1 & 7;
#pragma unroll
    for (int nt = 0; nt < 8; ++nt)
#pragma unroll
        for (int q = 0; q < 4; ++q) {
            int m  = nt * 8 + 2 * t + (q & 1);
            int my = m >> 3, mxc = m & 7;
            int ty = (q < 2) ? ty0 : ty1;
            int tx = (q < 2) ? tx0 : tx1;
            float v = cc[nt][q] * sc + bs[(ty - my + 7) * 15 + (tx - mxc + 7)];
            if (mhb && ((ty < 4) != (my < 4)))  v -= 100.0f;
            if (mwb && ((tx < 4) != (mxc < 4))) v -= 100.0f;
            cc[nt][q] = v;
        }

    float mx0 = -1e30f, mx1 = -1e30f;
#pragma unroll
    for (int nt = 0; nt < 8; ++nt) {
        mx0 = fmaxf(mx0, fmaxf(cc[nt][0], cc[nt][1]));
        mx1 = fmaxf(mx1, fmaxf(cc[nt][2], cc[nt][3]));
    }
    mx0 = fmaxf(mx0, __shfl_xor_sync(0xffffffffu, mx0, 1));
    mx0 = fmaxf(mx0, __shfl_xor_sync(0xffffffffu, mx0, 2));
    mx1 = fmaxf(mx1, __shfl_xor_sync(0xffffffffu, mx1, 1));
    mx1 = fmaxf(mx1, __shfl_xor_sync(0xffffffffu, mx1, 2));

    float s0 = 0.0f, s1 = 0.0f;
#pragma unroll
    for (int nt = 0; nt < 8; ++nt) {
        cc[nt][0] = __expf(cc[nt][0] - mx0);
        cc[nt][1] = __expf(cc[nt][1] - mx0);
        cc[nt][2] = __expf(cc[nt][2] - mx1);
        cc[nt][3] = __expf(cc[nt][3] - mx1);
        s0 += cc[nt][0] + cc[nt][1];
        s1 += cc[nt][2] + cc[nt][3];
    }
    s0 += __shfl_xor_sync(0xffffffffu, s0, 1);
    s0 += __shfl_xor_sync(0xffffffffu, s0, 2);
    s1 += __shfl_xor_sync(0xffffffffu, s1, 1);
    s1 += __shfl_xor_sync(0xffffffffu, s1, 2);
    const float inv0 = 1.0f / s0;
    const float inv1 = 1.0f / s1;

    unsigned* psw = ps[wt];
#pragma unroll
    for (int nt = 0; nt < 8; ++nt) {
        psw[g * 36 + nt * 4 + t]       = pkh(cc[nt][0], cc[nt][1]);
        psw[(g + 8) * 36 + nt * 4 + t] = pkh(cc[nt][2], cc[nt][3]);
    }
    __syncwarp();

    const unsigned ps_b  = (unsigned)__cvta_generic_to_shared(ps[wt]);
    const unsigned vts_b = (unsigned)__cvta_generic_to_shared(vts);
    float out[4][4];
#pragma unroll
    for (int vt = 0; vt < 4; ++vt)
#pragma unroll
        for (int q = 0; q < 4; ++q) out[vt][q] = 0.0f;

#pragma unroll
    for (int kb = 0; kb < 4; ++kb) {
        unsigned a4[4];
        ldsm4(a4, ps_b + alm * 144 + kb * 32 + alk);
#pragma unroll
        for (int vtp = 0; vtp < 2; ++vtp) {
            unsigned b4[4];
            ldsm4(b4, vts_b + (vtp * 16 + blm) * 144 + kb * 32 + blk);
            mma16(out[2 * vtp],     a4, b4);
            mma16(out[2 * vtp + 1], a4, b4 + 2);
        }
    }

    const int d0i = (((w << 6) | r0) << 8) + h * 32;
    const int d1i = (((w << 6) | r1) << 8) + h * 32;
    unsigned* ao32 = (unsigned*)g_ao;
#pragma unroll
    for (int vt = 0; vt < 4; ++vt) {
        ao32[(d0i + vt * 8 + 2 * t) >> 1] = pkh(out[vt][0] * inv0, out[vt][1] * inv0);
        ao32[(d1i + vt * 8 + 2 * t) >> 1] = pkh(out[vt][2] * inv1, out[vt][3] * inv1);
    }
}

// ============================================================
// Kernel 3: output projection, halved N tile, 3-stage, 2 CTAs/SM.
// ============================================================
__global__ void __launch_bounds__(512, 2)
swin_proj_kernel(const float* __restrict__ bo, float* __restrict__ out)
{
    extern __shared__ char smem[];
    const unsigned sb = (unsigned)__cvta_generic_to_shared(smem);
    float* bias_s = (float*)(smem + H_BIAS);

    const int bx   = blockIdx.x;
    const int bw   = bx >> 1;
    const int nh   = bx & 1;
    const int tid  = threadIdx.x;
    const int warp = tid >> 5;
    const int lane = tid & 31;
    const int g    = lane >> 2;
    const int t    = lane & 3;
    const int mw   = warp >> 2;
    const int nq   = warp & 3;

    const unsigned alm = lane & 15;
    const unsigned alk = (lane >> 4) << 4;
    const unsigned blm = (lane & 7) + ((lane >> 4) << 3);
    const unsigned blk = ((lane >> 3) & 1) << 4;

    if (tid < 128) bias_s[tid] = bo[nh * 128 + tid];
    __syncthreads();

    const int srow = tid >> 3;
    const int sjj  = tid & 7;
    const unsigned sto0 = srow * 144 + sjj * 16;
    const unsigned sto1 = (srow + 64) * 144 + sjj * 16;
    const unsigned short* wh = g_wh + 3 * 65536 + (nh << 15);
    const int abase = bw * 128 * 256;

#define STAGE(c_, st_) do {                                                    \
        unsigned _a = sb + H_BUF + (st_) * HSTG;                               \
        cp16(_a + sto0, g_ao + abase + srow * 256 + (c_) * 64 + sjj * 8);      \
        cp16(_a + sto1, g_ao + abase + (srow + 64) * 256 + (c_) * 64 + sjj * 8); \
        unsigned _bB = _a + HA_BYTES;                                          \
        cp16(_bB + sto0, wh + srow * 256 + (c_) * 64 + sjj * 8);               \
        cp16(_bB + sto1, wh + (srow + 64) * 256 + (c_) * 64 + sjj * 8);        \
        cp_commit();                                                           \
    } while (0)

    STAGE(0, 0); STAGE(1, 1); STAGE(2, 2);

    float acc[2][4][4];
#pragma unroll
    for (int mt = 0; mt < 2; ++mt)
#pragma unroll
        for (int nt = 0; nt < 4; ++nt)
#pragma unroll
            for (int q = 0; q < 4; ++q) acc[mt][nt][q] = 0.0f;

#pragma unroll 1
    for (int c = 0; c < 4; ++c) {
        if      (c == 0) cp_wait<2>();
        else if (c == 1) cp_wait<1>();
        else if (c == 2) cp_wait<1>();
        else             cp_wait<0>();
        __syncthreads();
        if (c == 1) STAGE(3, 0);

        const unsigned sbX = sb + H_BUF + (c % 3) * HSTG;
        const unsigned sbB = sbX + HA_BYTES;
#pragma unroll
        for (int ks = 0; ks < 4; ++ks) {
            unsigned a[2][4];
            ldsm4(a[0], sbX + (mw * 32 + alm) * 144 + ks * 32 + alk);
            ldsm4(a[1], sbX + (mw * 32 + 16 + alm) * 144 + ks * 32 + alk);
#pragma unroll
            for (int ntp = 0; ntp < 2; ++ntp) {
                unsigned b4[4];
                ldsm4(b4, sbB + (nq * 32 + ntp * 16 + blm) * 144 + ks * 32 + blk);
                mma16(acc[0][2 * ntp],     a[0], b4);
                mma16(acc[0][2 * ntp + 1], a[0], b4 + 2);
                mma16(acc[1][2 * ntp],     a[1], b4);
                mma16(acc[1][2 * ntp + 1], a[1], b4 + 2);
            }
        }
    }
#undef STAGE

    float2 bb[4];
#pragma unroll
    for (int nt = 0; nt < 4; ++nt)
        bb[nt] = *(float2*)(bias_s + nq * 32 + nt * 8 + 2 * t);

#pragma unroll
    for (int mt = 0; mt < 2; ++mt)
#pragma unroll
        for (int rh = 0; rh < 2; ++rh)
#pragma unroll
            for (int nt = 0; nt < 4; ++nt) {
                int n   = mw * 32 + mt * 16 + rh * 8 + g;
                int wv  = bw * 2 + (n >> 6);
                int tok = n & 63;
                int b   = wv >> 6, wy = (wv >> 3) & 7, wx = wv & 7;
                int y   = ((wy << 3) + (tok >> 3) + 4) & 63;
                int xc  = ((wx << 3) + (tok & 7) + 4) & 63;
                int col = nh * 128 + nq * 32 + nt * 8 + 2 * t;
                *(float2*)(out + (((b << 6) | y) << 14) + (xc << 8) + col) =
                    make_float2(acc[mt][nt][rh * 2] + bb[nt].x,
                                acc[mt][nt][rh * 2 + 1] + bb[nt].y);
            }
}

// ============================================================
extern "C" void kernel_launch(void* const* d_in, const int* in_sizes, int n_in,
                              void* d_out, int out_size)
{
    const float* x  = (const float*)d_in[0];
    const float* Wq = (const float*)d_in[1];
    const float* bq = (const float*)d_in[2];
    const float* Wk = (const float*)d_in[3];
    const float* bk = (const float*)d_in[4];
    const float* Wv = (const float*)d_in[5];
    const float* bv = (const float*)d_in[6];
    const float* Wo = (const float*)d_in[7];
    const float* bo = (const float*)d_in[8];
    const float* ls = (const float*)d_in[9];
    const float* w1 = (const float*)d_in[10];
    const float* b1 = (const float*)d_in[11];
    const float* w2 = (const float*)d_in[12];
    float* out = (float*)d_out;

    cudaFuncSetAttribute(swin_qkv_kernel,
                         cudaFuncAttributeMaxDynamicSharedMemorySize, H_SMEM);
    cudaFuncSetAttribute(swin_proj_kernel,
                         cudaFuncAttributeMaxDynamicSharedMemorySize, H_SMEM);

    swin_bias_kernel<<<225, 512>>>(ls, w1, b1, w2);
    swin_cvt_kernel<<<16640, 256>>>(x, Wq, Wk, Wv, Wo);
    swin_qkv_kernel<<<dim3(1024, 3), 512, H_SMEM>>>(bq, bk, bv);
    swin_attn_kernel<<<dim3(NWIN, NHEAD), 128>>>();
    swin_proj_kernel<<<1024, 512, H_SMEM>>>(bo, out);
}

// round 16
// speedup vs baseline: 1.0030x; 1.0030x over previous
#include <cuda_runtime.h>
#include <cuda_fp16.h>

// SwinV2 shifted-window attention, B=16, H=W=64, C=256, heads=8, hd=32.
// Round 16: attention L1-traffic cuts: (a) bias+mask precomputed into an
// fp32 table g_bm[type][head][64][64] (coalesced float2 loads replace 32
// scattered LDS + mask ALU per thread), (b) P kept in registers for PV
// (C-frag == A-frag identity; P smem staging deleted). GEMMs = round 14.

#define NWIN   1024
#define NTOK   64
#define CDIM   256
#define NHEAD  8
#define HD     32

// -------- scratch (device globals; no allocation) --------
__device__ unsigned       g_qh [NWIN * NHEAD * NTOK * 16];
__device__ unsigned       g_ql [NWIN * NHEAD * NTOK * 16];
__device__ unsigned       g_kh [NWIN * NHEAD * NTOK * 16];
__device__ unsigned       g_kl [NWIN * NHEAD * NTOK * 16];
__device__ unsigned       g_v16[NWIN * NHEAD * NTOK * 16];
__device__ unsigned short g_ao [NWIN * NTOK * CDIM];
__device__ unsigned short g_xh [16 * 64 * 64 * CDIM];
__device__ unsigned short g_wh [4 * CDIM * CDIM];
__device__ float          g_bias16[NHEAD * 225];
__device__ float          g_scale[NHEAD];
__device__ float          g_bm [4 * NHEAD * 64 * 64];   // bias+mask table

// -------- helpers --------
__device__ __forceinline__ unsigned pkh(float lo, float hi) {
    unsigned r;
    asm("cvt.rn.f16x2.f32 %0, %1, %2;" : "=r"(r) : "f"(hi), "f"(lo));
    return r;
}
__device__ __forceinline__ void mma16(float* c, const unsigned* a, const unsigned* b) {
    asm volatile("mma.sync.aligned.m16n8k16.row.col.f32.f16.f16.f32 "
                 "{%0,%1,%2,%3},{%4,%5,%6,%7},{%8,%9},{%0,%1,%2,%3};"
                 : "+f"(c[0]), "+f"(c[1]), "+f"(c[2]), "+f"(c[3])
                 : "r"(a[0]), "r"(a[1]), "r"(a[2]), "r"(a[3]),
                   "r"(b[0]), "r"(b[1]));
}
__device__ __forceinline__ void ldsm4(unsigned* r, unsigned addr) {
    asm volatile("ldmatrix.sync.aligned.m8n8.x4.shared.b16 {%0,%1,%2,%3}, [%4];"
                 : "=r"(r[0]), "=r"(r[1]), "=r"(r[2]), "=r"(r[3]) : "r"(addr));
}
__device__ __forceinline__ void cp16(unsigned dst, const void* src) {
    asm volatile("cp.async.cg.shared.global [%0], [%1], 16;" :: "r"(dst), "l"(src));
}
__device__ __forceinline__ void cp_commit() {
    asm volatile("cp.async.commit_group;");
}
template<int N> __device__ __forceinline__ void cp_wait() {
    asm volatile("cp.async.wait_group %0;" :: "n"(N));
}

// -------- halved-tile GEMM smem geometry: 3 resident stages, 2 CTAs/SM ----
#define HA_BYTES  (128 * 144)
#define HSTG      (2 * HA_BYTES)
#define H_ROWB    0
#define H_BIAS    512
#define H_BUF     2048
#define H_SMEM    (H_BUF + 3 * HSTG)

// ============================================================
// Kernel 0: continuous-position-bias MLP
// ============================================================
__global__ void swin_bias_kernel(const float* __restrict__ ls,
                                 const float* __restrict__ w1,
                                 const float* __restrict__ b1,
                                 const float* __restrict__ w2)
{
    __shared__ float part[16][8];
    const int t   = blockIdx.x;
    const int i   = t / 15;
    const int j   = t % 15;
    const int tid = threadIdx.x;
    const int warp = tid >> 5;
    const int lane = tid & 31;

    float rh = (float)(i - 7) * (8.0f / 7.0f);
    float rw = (float)(j - 7) * (8.0f / 7.0f);
    rh = copysignf(log2f(fabsf(rh) + 1.0f) * (1.0f / 3.0f), rh);
    rw = copysignf(log2f(fabsf(rw) + 1.0f) * (1.0f / 3.0f), rw);

    float hv = fmaxf(0.0f, rh * w1[tid] + rw * w1[512 + tid] + b1[tid]);

    float p[8];
#pragma unroll
    for (int h = 0; h < 8; ++h) p[h] = hv * w2[tid * 8 + h];
#pragma unroll
    for (int off = 16; off; off >>= 1)
#pragma unroll
        for (int h = 0; h < 8; ++h) p[h] += __shfl_xor_sync(0xffffffffu, p[h], off);
    if (lane == 0)
#pragma unroll
        for (int h = 0; h < 8; ++h) part[warp][h] = p[h];
    __syncthreads();

    if (tid < 8) {
        float s = 0.0f;
#pragma unroll
        for (int g = 0; g < 16; ++g) s += part[g][tid];
        g_bias16[tid * 225 + t] = 16.0f / (1.0f + expf(-s));
    }
    if (blockIdx.x == 0 && tid < 8)
        g_scale[tid] = expf(fminf(ls[tid], 4.6051701860f));
}

// ============================================================
// Kernel 0a: build bias+mask table  g_bm[type][head][r][m]
// grid 512 x 256
// ============================================================
__global__ void swin_bmtab_kernel()
{
    int idx  = blockIdx.x * 256 + threadIdx.x;
    int m    = idx & 63;
    int r    = (idx >> 6) & 63;
    int h    = (idx >> 12) & 7;
    int type = idx >> 15;
    int ty = r >> 3, tx = r & 7;
    int my = m >> 3, mx = m & 7;
    float v = g_bias16[h * 225 + (ty - my + 7) * 15 + (tx - mx + 7)];
    if ((type & 2) && ((ty < 4) != (my < 4))) v -= 100.0f;
    if ((type & 1) && ((tx < 4) != (mx < 4))) v -= 100.0f;
    g_bm[idx] = v;
}

// ============================================================
// Kernel 0b: x -> fp16; W -> transposed fp16 [n][k]
// ============================================================
__global__ void swin_cvt_kernel(const float* __restrict__ x,
                                const float* __restrict__ Wq,
                                const float* __restrict__ Wk,
                                const float* __restrict__ Wv,
                                const float* __restrict__ Wo)
{
    const int blk = blockIdx.x;
    const int tid = threadIdx.x;
    if (blk < 16384) {
        int i4 = blk * 256 + tid;
        float4 v = ((const float4*)x)[i4];
        ((uint2*)g_xh)[i4] = make_uint2(pkh(v.x, v.y), pkh(v.z, v.w));
    } else {
        int r = blk - 16384;
        int m = r >> 6;
        const float* W = (m == 0) ? Wq : (m == 1) ? Wk : (m == 2) ? Wv : Wo;
        int idx = (r & 63) * 256 + tid;
        int n  = idx >> 6;
        int k4 = (idx & 63) * 4;
        float a0 = W[(k4 + 0) * 256 + n];
        float a1 = W[(k4 + 1) * 256 + n];
        float a2 = W[(k4 + 2) * 256 + n];
        float a3 = W[(k4 + 3) * 256 + n];
        ((uint2*)(g_wh + m * 65536))[idx] = make_uint2(pkh(a0, a1), pkh(a2, a3));
    }
}

// ============================================================
// Kernel 1: QKV. grid (1024, 3). CTA M128xN128, 3-stage, 2 CTAs/SM.
// ============================================================
__global__ void __launch_bounds__(512, 2)
swin_qkv_kernel(const float* __restrict__ bq,
                const float* __restrict__ bk,
                const float* __restrict__ bv)
{
    extern __shared__ char smem[];
    const unsigned sb = (unsigned)__cvta_generic_to_shared(smem);
    unsigned* rowb_s = (unsigned*)(smem + H_ROWB);
    float*    bias_s = (float*)(smem + H_BIAS);

    const int bx   = blockIdx.x;
    const int bw   = bx >> 1;
    const int nh   = bx & 1;
    const int m    = blockIdx.y;
    const int tid  = threadIdx.x;
    const int warp = tid >> 5;
    const int lane = tid & 31;
    const int g    = lane >> 2;
    const int t    = lane & 3;
    const int mw   = warp >> 2;
    const int nq   = warp & 3;

    const unsigned alm = lane & 15;
    const unsigned alk = (lane >> 4) << 4;
    const unsigned blm = (lane & 7) + ((lane >> 4) << 3);
    const unsigned blk = ((lane >> 3) & 1) << 4;

    if (tid < 128) {
        int wv = bw * 2 + (tid >> 6);
        int b = wv >> 6, wy = (wv >> 3) & 7, wx = wv & 7;
        int tok = tid & 63;
        int sy = ((wy << 3) + (tok >> 3) + 4) & 63;
        int sx = ((wx << 3) + (tok & 7) + 4) & 63;
        rowb_s[tid] = ((((b << 6) | sy) << 6) | sx) << 8;
    }
    if (tid < 128) {
        const float* bp = (m == 0) ? bq : (m == 1) ? bk : bv;
        bias_s[tid] = bp[nh * 128 + tid];
    }
    __syncthreads();

    const int srow = tid >> 3;
    const int sjj  = tid & 7;
    const unsigned rb0 = rowb_s[srow];
    const unsigned rb1 = rowb_s[srow + 64];
    const unsigned sto0 = srow * 144 + sjj * 16;
    const unsigned sto1 = (srow + 64) * 144 + sjj * 16;
    const unsigned short* wh = g_wh + m * 65536 + (nh << 15);

#define STAGE(c_, st_) do {                                                    \
        unsigned _a = sb + H_BUF + (st_) * HSTG;                               \
        cp16(_a + sto0, g_xh + rb0 + (c_) * 64 + sjj * 8);                     \
        cp16(_a + sto1, g_xh + rb1 + (c_) * 64 + sjj * 8);                     \
        unsigned _bB = _a + HA_BYTES;                                          \
        cp16(_bB + sto0, wh + srow * 256 + (c_) * 64 + sjj * 8);               \
        cp16(_bB + sto1, wh + (srow + 64) * 256 + (c_) * 64 + sjj * 8);        \
        cp_commit();                                                           \
    } while (0)

    STAGE(0, 0); STAGE(1, 1); STAGE(2, 2);

    float acc[2][4][4];
#pragma unroll
    for (int mt = 0; mt < 2; ++mt)
#pragma unroll
        for (int nt = 0; nt < 4; ++nt)
#pragma unroll
            for (int q = 0; q < 4; ++q) acc[mt][nt][q] = 0.0f;

#pragma unroll 1
    for (int c = 0; c < 4; ++c) {
        if      (c == 0) cp_wait<2>();
        else if (c == 1) cp_wait<1>();
        else if (c == 2) cp_wait<1>();
        else             cp_wait<0>();
        __syncthreads();
        if (c == 1) STAGE(3, 0);

        const unsigned sbX = sb + H_BUF + (c % 3) * HSTG;
        const unsigned sbB = sbX + HA_BYTES;
#pragma unroll
        for (int ks = 0; ks < 4; ++ks) {
            unsigned a[2][4];
            ldsm4(a[0], sbX + (mw * 32 + alm) * 144 + ks * 32 + alk);
            ldsm4(a[1], sbX + (mw * 32 + 16 + alm) * 144 + ks * 32 + alk);
#pragma unroll
            for (int ntp = 0; ntp < 2; ++ntp) {
                unsigned b4[4];
                ldsm4(b4, sbB + (nq * 32 + ntp * 16 + blm) * 144 + ks * 32 + blk);
                mma16(acc[0][2 * ntp],     a[0], b4);
                mma16(acc[0][2 * ntp + 1], a[0], b4 + 2);
                mma16(acc[1][2 * ntp],     a[1], b4);
                mma16(acc[1][2 * ntp + 1], a[1], b4 + 2);
            }
        }
    }
#undef STAGE

    const int head = nh * 4 + nq;
    float2 bb[4];
#pragma unroll
    for (int nt = 0; nt < 4; ++nt)
        bb[nt] = *(float2*)(bias_s + nq * 32 + nt * 8 + 2 * t);
#pragma unroll
    for (int mt = 0; mt < 2; ++mt)
#pragma unroll
        for (int nt = 0; nt < 4; ++nt) {
            acc[mt][nt][0] += bb[nt].x;  acc[mt][nt][1] += bb[nt].y;
            acc[mt][nt][2] += bb[nt].x;  acc[mt][nt][3] += bb[nt].y;
        }

    if (m < 2) {
#pragma unroll
        for (int mt = 0; mt < 2; ++mt)
#pragma unroll
            for (int rh = 0; rh < 2; ++rh) {
                float s = 0.0f;
#pragma unroll
                for (int nt = 0; nt < 4; ++nt)
                    s += acc[mt][nt][rh * 2]     * acc[mt][nt][rh * 2]
                       + acc[mt][nt][rh * 2 + 1] * acc[mt][nt][rh * 2 + 1];
                s += __shfl_xor_sync(0xffffffffu, s, 1);
                s += __shfl_xor_sync(0xffffffffu, s, 2);
                float inv = 1.0f / fmaxf(sqrtf(s), 1e-12f);
#pragma unroll
                for (int nt = 0; nt < 4; ++nt) {
                    acc[mt][nt][rh * 2]     *= inv;
                    acc[mt][nt][rh * 2 + 1] *= inv;
                }
            }
    }

#pragma unroll
    for (int mt = 0; mt < 2; ++mt)
#pragma unroll
        for (int rh = 0; rh < 2; ++rh)
#pragma unroll
            for (int nt = 0; nt < 4; ++nt) {
                int n    = mw * 32 + mt * 16 + rh * 8 + g;
                int win  = bw * 2 + (n >> 6);
                int tok  = n & 63;
                int d    = nt * 8 + 2 * t;
                int idx  = (((win << 3) | head) << 10) + (tok << 4) + (d >> 1);
                float vx = acc[mt][nt][rh * 2];
                float vy = acc[mt][nt][rh * 2 + 1];
                if (m == 2) {
                    g_v16[idx] = pkh(vx, vy);
                } else {
                    unsigned hw = pkh(vx, vy);
                    float2 hf = __half22float2(*(__half2*)&hw);
                    unsigned lw = pkh(vx - hf.x, vy - hf.y);
                    if (m == 0) { g_qh[idx] = hw; g_ql[idx] = lw; }
                    else        { g_kh[idx] = hw; g_kl[idx] = lw; }
                }
            }
}

// ============================================================
// Kernel 2: fully-fp16 MMA attention. grid (1024, 8), 128 threads.
// Register-resident P; bias+mask from g_bm (coalesced fp32 loads).
// ============================================================
__global__ void __launch_bounds__(128, 6)
swin_attn_kernel()
{
    __shared__ __align__(16) unsigned khs[64 * 20];
    __shared__ __align__(16) unsigned kls[64 * 20];
    __shared__ __align__(16) unsigned vts[32 * 36];

    const int w    = blockIdx.x;
    const int h    = blockIdx.y;
    const int tid  = threadIdx.x;
    const int wt   = tid >> 5;
    const int lane = tid & 31;
    const int g    = lane >> 2;
    const int t    = lane & 3;
    const int pbase = ((w << 3) | h) << 10;

    const unsigned blm = (lane & 7) + ((lane >> 4) << 3);
    const unsigned blk = ((lane >> 3) & 1) << 4;

    const unsigned khs_b = (unsigned)__cvta_generic_to_shared(khs);
    const unsigned kls_b = (unsigned)__cvta_generic_to_shared(kls);

    // ---- stage K hi/lo via cp.async ----
#pragma unroll
    for (int it = 0; it < 2; ++it) {
        int i4  = tid + it * 128;
        int row = i4 >> 2;
        int c4  = (i4 & 3) << 2;
        unsigned off = (row * 20 + c4) << 2;
        cp16(khs_b + off, g_kh + pbase + i4 * 4);
        cp16(kls_b + off, g_kl + pbase + i4 * 4);
    }
    cp_commit();

    // ---- stage V^T while K copies fly ----
    {
        const int mp = tid & 31;
        const int dp = tid >> 5;
        const uint4* v4 = (const uint4*)(g_v16 + pbase);
        uint4 a = v4[(2 * mp) * 4 + dp];
        uint4 b = v4[(2 * mp + 1) * 4 + dp];
        int d0 = dp * 8;
        vts[(d0 + 0) * 36 + mp] = __byte_perm(a.x, b.x, 0x5410);
        vts[(d0 + 1) * 36 + mp] = __byte_perm(a.x, b.x, 0x7632);
        vts[(d0 + 2) * 36 + mp] = __byte_perm(a.y, b.y, 0x5410);
        vts[(d0 + 3) * 36 + mp] = __byte_perm(a.y, b.y, 0x7632);
        vts[(d0 + 4) * 36 + mp] = __byte_perm(a.z, b.z, 0x5410);
        vts[(d0 + 5) * 36 + mp] = __byte_perm(a.z, b.z, 0x7632);
        vts[(d0 + 6) * 36 + mp] = __byte_perm(a.w, b.w, 0x5410);
        vts[(d0 + 7) * 36 + mp] = __byte_perm(a.w, b.w, 0x7632);
    }

    const float sc = g_scale[h];
    const int wy = (w >> 3) & 7, wx = w & 7;
    const int type = ((wy == 7) ? 2 : 0) | ((wx == 7) ? 1 : 0);
    const float* bmr = g_bm + (((type << 3) | h) << 12);
    const int r0 = wt * 16 + g;
    const int r1 = r0 + 8;

    // ---- Q fragments ----
    const unsigned* qhp = g_qh + pbase;
    const unsigned* qlp = g_ql + pbase;
    unsigned aqh[2][4], aql[2][4];
#pragma unroll
    for (int ks = 0; ks < 2; ++ks) {
        int bidx = r0 * 16 + ks * 8 + t;
        aqh[ks][0] = qhp[bidx];        aqh[ks][1] = qhp[bidx + 128];
        aqh[ks][2] = qhp[bidx + 4];    aqh[ks][3] = qhp[bidx + 132];
        aql[ks][0] = qlp[bidx];        aql[ks][1] = qlp[bidx + 128];
        aql[ks][2] = qlp[bidx + 4];    aql[ks][3] = qlp[bidx + 132];
    }

    cp_wait<0>();
    __syncthreads();

    // ---- QK^T (fp16 hi/lo 3-term) ----
    float cc[8][4];
#pragma unroll
    for (int nt = 0; nt < 8; ++nt)
#pragma unroll
        for (int q = 0; q < 4; ++q) cc[nt][q] = 0.0f;

#pragma unroll
    for (int ks = 0; ks < 2; ++ks) {
#pragma unroll
        for (int ntp = 0; ntp < 4; ++ntp) {
            unsigned off = (ntp * 16 + blm) * 80 + ks * 32 + blk;
            unsigned rh4[4], rl4[4];
            ldsm4(rh4, khs_b + off);
            ldsm4(rl4, kls_b + off);
            mma16(cc[2 * ntp],     aqh[ks], rh4);
            mma16(cc[2 * ntp],     aql[ks], rh4);
            mma16(cc[2 * ntp],     aqh[ks], rl4);
            mma16(cc[2 * ntp + 1], aqh[ks], rh4 + 2);
            mma16(cc[2 * ntp + 1], aql[ks], rh4 + 2);
            mma16(cc[2 * ntp + 1], aqh[ks], rl4 + 2);
        }
    }

    // ---- bias + mask from table (coalesced) ----
#pragma unroll
    for (int nt = 0; nt < 8; ++nt) {
        float2 b0 = *(const float2*)(bmr + (r0 << 6) + nt * 8 + 2 * t);
        float2 b1 = *(const float2*)(bmr + (r1 << 6) + nt * 8 + 2 * t);
        cc[nt][0] = cc[nt][0] * sc + b0.x;
        cc[nt][1] = cc[nt][1] * sc + b0.y;
        cc[nt][2] = cc[nt][2] * sc + b1.x;
        cc[nt][3] = cc[nt][3] * sc + b1.y;
    }

    // ---- softmax ----
    float mx0 = -1e30f, mx1 = -1e30f;
#pragma unroll
    for (int nt = 0; nt < 8; ++nt) {
        mx0 = fmaxf(mx0, fmaxf(cc[nt][0], cc[nt][1]));
        mx1 = fmaxf(mx1, fmaxf(cc[nt][2], cc[nt][3]));
    }
    mx0 = fmaxf(mx0, __shfl_xor_sync(0xffffffffu, mx0, 1));
    mx0 = fmaxf(mx0, __shfl_xor_sync(0xffffffffu, mx0, 2));
    mx1 = fmaxf(mx1, __shfl_xor_sync(0xffffffffu, mx1, 1));
    mx1 = fmaxf(mx1, __shfl_xor_sync(0xffffffffu, mx1, 2));

    float s0 = 0.0f, s1 = 0.0f;
#pragma unroll
    for (int nt = 0; nt < 8; ++nt) {
        cc[nt][0] = __expf(cc[nt][0] - mx0);
        cc[nt][1] = __expf(cc[nt][1] - mx0);
        cc[nt][2] = __expf(cc[nt][2] - mx1);
        cc[nt][3] = __expf(cc[nt][3] - mx1);
        s0 += cc[nt][0] + cc[nt][1];
        s1 += cc[nt][2] + cc[nt][3];
    }
    s0 += __shfl_xor_sync(0xffffffffu, s0, 1);
    s0 += __shfl_xor_sync(0xffffffffu, s0, 2);
    s1 += __shfl_xor_sync(0xffffffffu, s1, 1);
    s1 += __shfl_xor_sync(0xffffffffu, s1, 2);
    const float inv0 = 1.0f / s0;
    const float inv1 = 1.0f / s1;

    // ---- PV: P fragments packed straight from cc (no smem round trip) ----
    const unsigned vts_b = (unsigned)__cvta_generic_to_shared(vts);
    float out[4][4];
#pragma unroll
    for (int vt = 0; vt < 4; ++vt)
#pragma unroll
        for (int q = 0; q < 4; ++q) out[vt][q] = 0.0f;

#pragma unroll
    for (int kb = 0; kb < 4; ++kb) {
        unsigned a4[4] = {
            pkh(cc[2 * kb][0],     cc[2 * kb][1]),
            pkh(cc[2 * kb][2],     cc[2 * kb][3]),
            pkh(cc[2 * kb + 1][0], cc[2 * kb + 1][1]),
            pkh(cc[2 * kb + 1][2], cc[2 * kb + 1][3]) };
#pragma unroll
        for (int vtp = 0; vtp < 2; ++vtp) {
            unsigned b4[4];
            ldsm4(b4, vts_b + (vtp * 16 + blm) * 144 + kb * 32 + blk);
            mma16(out[2 * vtp],     a4, b4);
            mma16(out[2 * vtp + 1], a4, b4 + 2);
        }
    }

    const int d0i = (((w << 6) | r0) << 8) + h * 32;
    const int d1i = (((w << 6) | r1) << 8) + h * 32;
    unsigned* ao32 = (unsigned*)g_ao;
#pragma unroll
    for (int vt = 0; vt < 4; ++vt) {
        ao32[(d0i + vt * 8 + 2 * t) >> 1] = pkh(out[vt][0] * inv0, out[vt][1] * inv0);
        ao32[(d1i + vt * 8 + 2 * t) >> 1] = pkh(out[vt][2] * inv1, out[vt][3] * inv1);
    }
}

// ============================================================
// Kernel 3: output projection, halved N tile, 3-stage, 2 CTAs/SM.
// ============================================================
__global__ void __launch_bounds__(512, 2)
swin_proj_kernel(const float* __restrict__ bo, float* __restrict__ out)
{
    extern __shared__ char smem[];
    const unsigned sb = (unsigned)__cvta_generic_to_shared(smem);
    float* bias_s = (float*)(smem + H_BIAS);

    const int bx   = blockIdx.x;
    const int bw   = bx >> 1;
    const int nh   = bx & 1;
    const int tid  = threadIdx.x;
    const int warp = tid >> 5;
    const int lane = tid & 31;
    const int g    = lane >> 2;
    const int t    = lane & 3;
    const int mw   = warp >> 2;
    const int nq   = warp & 3;

    const unsigned alm = lane & 15;
    const unsigned alk = (lane >> 4) << 4;
    const unsigned blm = (lane & 7) + ((lane >> 4) << 3);
    const unsigned blk = ((lane >> 3) & 1) << 4;

    if (tid < 128) bias_s[tid] = bo[nh * 128 + tid];
    __syncthreads();

    const int srow = tid >> 3;
    const int sjj  = tid & 7;
    const unsigned sto0 = srow * 144 + sjj * 16;
    const unsigned sto1 = (srow + 64) * 144 + sjj * 16;
    const unsigned short* wh = g_wh + 3 * 65536 + (nh << 15);
    const int abase = bw * 128 * 256;

#define STAGE(c_, st_) do {                                                    \
        unsigned _a = sb + H_BUF + (st_) * HSTG;                               \
        cp16(_a + sto0, g_ao + abase + srow * 256 + (c_) * 64 + sjj * 8);      \
        cp16(_a + sto1, g_ao + abase + (srow + 64) * 256 + (c_) * 64 + sjj * 8); \
        unsigned _bB = _a + HA_BYTES;                                          \
        cp16(_bB + sto0, wh + srow * 256 + (c_) * 64 + sjj * 8);               \
        cp16(_bB + sto1, wh + (srow + 64) * 256 + (c_) * 64 + sjj * 8);        \
        cp_commit();                                                           \
    } while (0)

    STAGE(0, 0); STAGE(1, 1); STAGE(2, 2);

    float acc[2][4][4];
#pragma unroll
    for (int mt = 0; mt < 2; ++mt)
#pragma unroll
        for (int nt = 0; nt < 4; ++nt)
#pragma unroll
            for (int q = 0; q < 4; ++q) acc[mt][nt][q] = 0.0f;

#pragma unroll 1
    for (int c = 0; c < 4; ++c) {
        if      (c == 0) cp_wait<2>();
        else if (c == 1) cp_wait<1>();
        else if (c == 2) cp_wait<1>();
        else             cp_wait<0>();
        __syncthreads();
        if (c == 1) STAGE(3, 0);

        const unsigned sbX = sb + H_BUF + (c % 3) * HSTG;
        const unsigned sbB = sbX + HA_BYTES;
#pragma unroll
        for (int ks = 0; ks < 4; ++ks) {
            unsigned a[2][4];
            ldsm4(a[0], sbX + (mw * 32 + alm) * 144 + ks * 32 + alk);
            ldsm4(a[1], sbX + (mw * 32 + 16 + alm) * 144 + ks * 32 + alk);
#pragma unroll
            for (int ntp = 0; ntp < 2; ++ntp) {
                unsigned b4[4];
                ldsm4(b4, sbB + (nq * 32 + ntp * 16 + blm) * 144 + ks * 32 + blk);
                mma16(acc[0][2 * ntp],     a[0], b4);
                mma16(acc[0][2 * ntp + 1], a[0], b4 + 2);
                mma16(acc[1][2 * ntp],     a[1], b4);
                mma16(acc[1][2 * ntp + 1], a[1], b4 + 2);
            }
        }
    }
#undef STAGE

    float2 bb[4];
#pragma unroll
    for (int nt = 0; nt < 4; ++nt)
        bb[nt] = *(float2*)(bias_s + nq * 32 + nt * 8 + 2 * t);

#pragma unroll
    for (int mt = 0; mt < 2; ++mt)
#pragma unroll
        for (int rh = 0; rh < 2; ++rh)
#pragma unroll
            for (int nt = 0; nt < 4; ++nt) {
                int n   = mw * 32 + mt * 16 + rh * 8 + g;
                int wv  = bw * 2 + (n >> 6);
                int tok = n & 63;
                int b   = wv >> 6, wy = (wv >> 3) & 7, wx = wv & 7;
                int y   = ((wy << 3) + (tok >> 3) + 4) & 63;
                int xc  = ((wx << 3) + (tok & 7) + 4) & 63;
                int col = nh * 128 + nq * 32 + nt * 8 + 2 * t;
                *(float2*)(out + (((b << 6) | y) << 14) + (xc << 8) + col) =
                    make_float2(acc[mt][nt][rh * 2] + bb[nt].x,
                                acc[mt][nt][rh * 2 + 1] + bb[nt].y);
            }
}

// ============================================================
extern "C" void kernel_launch(void* const* d_in, const int* in_sizes, int n_in,
                              void* d_out, int out_size)
{
    const float* x  = (const float*)d_in[0];
    const float* Wq = (const float*)d_in[1];
    const float* bq = (const float*)d_in[2];
    const float* Wk = (const float*)d_in[3];
    const float* bk = (const float*)d_in[4];
    const float* Wv = (const float*)d_in[5];
    const float* bv = (const float*)d_in[6];
    const float* Wo = (const float*)d_in[7];
    const float* bo = (const float*)d_in[8];
    const float* ls = (const float*)d_in[9];
    const float* w1 = (const float*)d_in[10];
    const float* b1 = (const float*)d_in[11];
    const float* w2 = (const float*)d_in[12];
    float* out = (float*)d_out;

    cudaFuncSetAttribute(swin_qkv_kernel,
                         cudaFuncAttributeMaxDynamicSharedMemorySize, H_SMEM);
    cudaFuncSetAttribute(swin_proj_kernel,
                         cudaFuncAttributeMaxDynamicSharedMemorySize, H_SMEM);

    swin_bias_kernel<<<225, 512>>>(ls, w1, b1, w2);
    swin_bmtab_kernel<<<512, 256>>>();
    swin_cvt_kernel<<<16640, 256>>>(x, Wq, Wk, Wv, Wo);
    swin_qkv_kernel<<<dim3(1024, 3), 512, H_SMEM>>>(bq, bk, bv);
    swin_attn_kernel<<<dim3(NWIN, NHEAD), 128>>>();
    swin_proj_kernel<<<1024, 512, H_SMEM>>>(bo, out);
}

// round 17
// speedup vs baseline: 1.0190x; 1.0159x over previous
#include <cuda_runtime.h>
#include <cuda_fp16.h>

// SwinV2 shifted-window attention, B=16, H=W=64, C=256, heads=8, hd=32.
// Round 17: GEMM warp tile enlarged to M64xN64 (4 warps / 128 threads per
// CTA, ldsm:mma 1:4 -> L1 wavefronts halved per FLOP, 32 independent MMA
// chains per warp). CTA still M128xN128, 3-stage cp.async, 2 CTAs/SM.
// Attention/bias/bmtab/cvt identical to round 16.

#define NWIN   1024
#define NTOK   64
#define CDIM   256
#define NHEAD  8
#define HD     32

// -------- scratch (device globals; no allocation) --------
__device__ unsigned       g_qh [NWIN * NHEAD * NTOK * 16];
__device__ unsigned       g_ql [NWIN * NHEAD * NTOK * 16];
__device__ unsigned       g_kh [NWIN * NHEAD * NTOK * 16];
__device__ unsigned       g_kl [NWIN * NHEAD * NTOK * 16];
__device__ unsigned       g_v16[NWIN * NHEAD * NTOK * 16];
__device__ unsigned short g_ao [NWIN * NTOK * CDIM];
__device__ unsigned short g_xh [16 * 64 * 64 * CDIM];
__device__ unsigned short g_wh [4 * CDIM * CDIM];
__device__ float          g_bias16[NHEAD * 225];
__device__ float          g_scale[NHEAD];
__device__ float          g_bm [4 * NHEAD * 64 * 64];

// -------- helpers --------
__device__ __forceinline__ unsigned pkh(float lo, float hi) {
    unsigned r;
    asm("cvt.rn.f16x2.f32 %0, %1, %2;" : "=r"(r) : "f"(hi), "f"(lo));
    return r;
}
__device__ __forceinline__ void mma16(float* c, const unsigned* a, const unsigned* b) {
    asm volatile("mma.sync.aligned.m16n8k16.row.col.f32.f16.f16.f32 "
                 "{%0,%1,%2,%3},{%4,%5,%6,%7},{%8,%9},{%0,%1,%2,%3};"
                 : "+f"(c[0]), "+f"(c[1]), "+f"(c[2]), "+f"(c[3])
                 : "r"(a[0]), "r"(a[1]), "r"(a[2]), "r"(a[3]),
                   "r"(b[0]), "r"(b[1]));
}
__device__ __forceinline__ void ldsm4(unsigned* r, unsigned addr) {
    asm volatile("ldmatrix.sync.aligned.m8n8.x4.shared.b16 {%0,%1,%2,%3}, [%4];"
                 : "=r"(r[0]), "=r"(r[1]), "=r"(r[2]), "=r"(r[3]) : "r"(addr));
}
__device__ __forceinline__ void cp16(unsigned dst, const void* src) {
    asm volatile("cp.async.cg.shared.global [%0], [%1], 16;" :: "r"(dst), "l"(src));
}
__device__ __forceinline__ void cp_commit() {
    asm volatile("cp.async.commit_group;");
}
template<int N> __device__ __forceinline__ void cp_wait() {
    asm volatile("cp.async.wait_group %0;" :: "n"(N));
}

// -------- GEMM smem geometry: M128xN128 CTA, 3 stages, 2 CTAs/SM --------
#define QA_BYTES  (128 * 144)
#define QSTG      (2 * QA_BYTES)
#define H_ROWB    0
#define H_BIAS    512
#define H_BUF     2048
#define H_SMEM    (H_BUF + 3 * QSTG)   // 112640

// ============================================================
// Kernel 0: continuous-position-bias MLP
// ============================================================
__global__ void swin_bias_kernel(const float* __restrict__ ls,
                                 const float* __restrict__ w1,
                                 const float* __restrict__ b1,
                                 const float* __restrict__ w2)
{
    __shared__ float part[16][8];
    const int t   = blockIdx.x;
    const int i   = t / 15;
    const int j   = t % 15;
    const int tid = threadIdx.x;
    const int warp = tid >> 5;
    const int lane = tid & 31;

    float rh = (float)(i - 7) * (8.0f / 7.0f);
    float rw = (float)(j - 7) * (8.0f / 7.0f);
    rh = copysignf(log2f(fabsf(rh) + 1.0f) * (1.0f / 3.0f), rh);
    rw = copysignf(log2f(fabsf(rw) + 1.0f) * (1.0f / 3.0f), rw);

    float hv = fmaxf(0.0f, rh * w1[tid] + rw * w1[512 + tid] + b1[tid]);

    float p[8];
#pragma unroll
    for (int h = 0; h < 8; ++h) p[h] = hv * w2[tid * 8 + h];
#pragma unroll
    for (int off = 16; off; off >>= 1)
#pragma unroll
        for (int h = 0; h < 8; ++h) p[h] += __shfl_xor_sync(0xffffffffu, p[h], off);
    if (lane == 0)
#pragma unroll
        for (int h = 0; h < 8; ++h) part[warp][h] = p[h];
    __syncthreads();

    if (tid < 8) {
        float s = 0.0f;
#pragma unroll
        for (int g = 0; g < 16; ++g) s += part[g][tid];
        g_bias16[tid * 225 + t] = 16.0f / (1.0f + expf(-s));
    }
    if (blockIdx.x == 0 && tid < 8)
        g_scale[tid] = expf(fminf(ls[tid], 4.6051701860f));
}

// ============================================================
// Kernel 0a: bias+mask table  g_bm[type][head][r][m]
// ============================================================
__global__ void swin_bmtab_kernel()
{
    int idx  = blockIdx.x * 256 + threadIdx.x;
    int m    = idx & 63;
    int r    = (idx >> 6) & 63;
    int h    = (idx >> 12) & 7;
    int type = idx >> 15;
    int ty = r >> 3, tx = r & 7;
    int my = m >> 3, mx = m & 7;
    float v = g_bias16[h * 225 + (ty - my + 7) * 15 + (tx - mx + 7)];
    if ((type & 2) && ((ty < 4) != (my < 4))) v -= 100.0f;
    if ((type & 1) && ((tx < 4) != (mx < 4))) v -= 100.0f;
    g_bm[idx] = v;
}

// ============================================================
// Kernel 0b: x -> fp16; W -> transposed fp16 [n][k]
// ============================================================
__global__ void swin_cvt_kernel(const float* __restrict__ x,
                                const float* __restrict__ Wq,
                                const float* __restrict__ Wk,
                                const float* __restrict__ Wv,
                                const float* __restrict__ Wo)
{
    const int blk = blockIdx.x;
    const int tid = threadIdx.x;
    if (blk < 16384) {
        int i4 = blk * 256 + tid;
        float4 v = ((const float4*)x)[i4];
        ((uint2*)g_xh)[i4] = make_uint2(pkh(v.x, v.y), pkh(v.z, v.w));
    } else {
        int r = blk - 16384;
        int m = r >> 6;
        const float* W = (m == 0) ? Wq : (m == 1) ? Wk : (m == 2) ? Wv : Wo;
        int idx = (r & 63) * 256 + tid;
        int n  = idx >> 6;
        int k4 = (idx & 63) * 4;
        float a0 = W[(k4 + 0) * 256 + n];
        float a1 = W[(k4 + 1) * 256 + n];
        float a2 = W[(k4 + 2) * 256 + n];
        float a3 = W[(k4 + 3) * 256 + n];
        ((uint2*)(g_wh + m * 65536))[idx] = make_uint2(pkh(a0, a1), pkh(a2, a3));
    }
}

// ============================================================
// Kernel 1: QKV. grid (1024, 3): x = bw*2+nh, y = 0:Q,1:K,2:V.
// CTA M128xN128, 128 threads (4 warps), warp tile M64xN64.
// ============================================================
__global__ void __launch_bounds__(128)
swin_qkv_kernel(const float* __restrict__ bq,
                const float* __restrict__ bk,
                const float* __restrict__ bv)
{
    extern __shared__ char smem[];
    const unsigned sb = (unsigned)__cvta_generic_to_shared(smem);
    unsigned* rowb_s = (unsigned*)(smem + H_ROWB);
    float*    bias_s = (float*)(smem + H_BIAS);

    const int bx   = blockIdx.x;
    const int bw   = bx >> 1;
    const int nh   = bx & 1;
    const int m    = blockIdx.y;
    const int tid  = threadIdx.x;
    const int warp = tid >> 5;
    const int lane = tid & 31;
    const int g    = lane >> 2;
    const int t    = lane & 3;
    const int mw   = warp >> 1;           // M 64-slice (0..1)
    const int nqw  = warp & 1;            // N 64-slice (0..1)

    const unsigned alm = lane & 15;
    const unsigned alk = (lane >> 4) << 4;
    const unsigned blm = (lane & 7) + ((lane >> 4) << 3);
    const unsigned blk = ((lane >> 3) & 1) << 4;

    {
        int wv = bw * 2 + (tid >> 6);
        int b = wv >> 6, wy = (wv >> 3) & 7, wx = wv & 7;
        int tok = tid & 63;
        int sy = ((wy << 3) + (tok >> 3) + 4) & 63;
        int sx = ((wx << 3) + (tok & 7) + 4) & 63;
        rowb_s[tid] = ((((b << 6) | sy) << 6) | sx) << 8;
        const float* bp = (m == 0) ? bq : (m == 1) ? bk : bv;
        bias_s[tid] = bp[nh * 128 + tid];
    }
    __syncthreads();

    const int srow = tid >> 3;            // 0..15
    const int sjj  = tid & 7;
    unsigned rb[8];
#pragma unroll
    for (int i = 0; i < 8; ++i) rb[i] = rowb_s[srow + 16 * i];
    const unsigned short* wh = g_wh + m * 65536 + (nh << 15);

#define STAGE(c_, st_) do {                                                    \
        unsigned _a = sb + H_BUF + (st_) * QSTG;                               \
        _Pragma("unroll")                                                      \
        for (int _i = 0; _i < 8; ++_i) {                                       \
            int _r = srow + 16 * _i;                                           \
            cp16(_a + _r * 144 + sjj * 16, g_xh + rb[_i] + (c_) * 64 + sjj * 8); \
        }                                                                      \
        unsigned _bB = _a + QA_BYTES;                                          \
        _Pragma("unroll")                                                      \
        for (int _i = 0; _i < 8; ++_i) {                                       \
            int _r = srow + 16 * _i;                                           \
            cp16(_bB + _r * 144 + sjj * 16, wh + _r * 256 + (c_) * 64 + sjj * 8); \
        }                                                                      \
        cp_commit();                                                           \
    } while (0)

    STAGE(0, 0); STAGE(1, 1); STAGE(2, 2);

    float acc[4][8][4];
#pragma unroll
    for (int mt = 0; mt < 4; ++mt)
#pragma unroll
        for (int nt = 0; nt < 8; ++nt)
#pragma unroll
            for (int q = 0; q < 4; ++q) acc[mt][nt][q] = 0.0f;

#pragma unroll 1
    for (int c = 0; c < 4; ++c) {
        if      (c == 0) cp_wait<2>();
        else if (c == 1) cp_wait<1>();
        else if (c == 2) cp_wait<1>();
        else             cp_wait<0>();
        __syncthreads();
        if (c == 1) STAGE(3, 0);

        const unsigned sbX = sb + H_BUF + (c % 3) * QSTG;
        const unsigned sbB = sbX + QA_BYTES;
#pragma unroll
        for (int ks = 0; ks < 4; ++ks) {
            unsigned a[4][4];
#pragma unroll
            for (int mt = 0; mt < 4; ++mt)
                ldsm4(a[mt], sbX + (mw * 64 + mt * 16 + alm) * 144 + ks * 32 + alk);
#pragma unroll
            for (int ntp = 0; ntp < 4; ++ntp) {
                unsigned b4[4];
                ldsm4(b4, sbB + (nqw * 64 + ntp * 16 + blm) * 144 + ks * 32 + blk);
#pragma unroll
                for (int mt = 0; mt < 4; ++mt) {
                    mma16(acc[mt][2 * ntp],     a[mt], b4);
                    mma16(acc[mt][2 * ntp + 1], a[mt], b4 + 2);
                }
            }
        }
    }
#undef STAGE

    // ---- epilogue: warp covers 2 heads (hh = nt>>2) ----
    const int headbase = nh * 4 + nqw * 2;
    float2 bb[8];
#pragma unroll
    for (int nt = 0; nt < 8; ++nt)
        bb[nt] = *(float2*)(bias_s + nqw * 64 + nt * 8 + 2 * t);
#pragma unroll
    for (int mt = 0; mt < 4; ++mt)
#pragma unroll
        for (int nt = 0; nt < 8; ++nt) {
            acc[mt][nt][0] += bb[nt].x;  acc[mt][nt][1] += bb[nt].y;
            acc[mt][nt][2] += bb[nt].x;  acc[mt][nt][3] += bb[nt].y;
        }

    if (m < 2) {   // cosine normalization per head (32 dims)
#pragma unroll
        for (int mt = 0; mt < 4; ++mt)
#pragma unroll
            for (int rh = 0; rh < 2; ++rh)
#pragma unroll
                for (int hh = 0; hh < 2; ++hh) {
                    float s = 0.0f;
#pragma unroll
                    for (int k2 = 0; k2 < 4; ++k2) {
                        int nt = hh * 4 + k2;
                        s += acc[mt][nt][rh * 2]     * acc[mt][nt][rh * 2]
                           + acc[mt][nt][rh * 2 + 1] * acc[mt][nt][rh * 2 + 1];
                    }
                    s += __shfl_xor_sync(0xffffffffu, s, 1);
                    s += __shfl_xor_sync(0xffffffffu, s, 2);
                    float inv = 1.0f / fmaxf(sqrtf(s), 1e-12f);
#pragma unroll
                    for (int k2 = 0; k2 < 4; ++k2) {
                        int nt = hh * 4 + k2;
                        acc[mt][nt][rh * 2]     *= inv;
                        acc[mt][nt][rh * 2 + 1] *= inv;
                    }
                }
    }

#pragma unroll
    for (int mt = 0; mt < 4; ++mt)
#pragma unroll
        for (int rh = 0; rh < 2; ++rh)
#pragma unroll
            for (int nt = 0; nt < 8; ++nt) {
                int n    = mw * 64 + mt * 16 + rh * 8 + g;
                int win  = bw * 2 + (n >> 6);
                int tok  = n & 63;
                int head = headbase + (nt >> 2);
                int d    = (nt & 3) * 8 + 2 * t;
                int idx  = (((win << 3) | head) << 10) + (tok << 4) + (d >> 1);
                float vx = acc[mt][nt][rh * 2];
                float vy = acc[mt][nt][rh * 2 + 1];
                if (m == 2) {
                    g_v16[idx] = pkh(vx, vy);
                } else {
                    unsigned hw = pkh(vx, vy);
                    float2 hf = __half22float2(*(__half2*)&hw);
                    unsigned lw = pkh(vx - hf.x, vy - hf.y);
                    if (m == 0) { g_qh[idx] = hw; g_ql[idx] = lw; }
                    else        { g_kh[idx] = hw; g_kl[idx] = lw; }
                }
            }
}

// ============================================================
// Kernel 2: fully-fp16 MMA attention (round 16, unchanged).
// ============================================================
__global__ void __launch_bounds__(128, 6)
swin_attn_kernel()
{
    __shared__ __align__(16) unsigned khs[64 * 20];
    __shared__ __align__(16) unsigned kls[64 * 20];
    __shared__ __align__(16) unsigned vts[32 * 36];

    const int w    = blockIdx.x;
    const int h    = blockIdx.y;
    const int tid  = threadIdx.x;
    const int wt   = tid >> 5;
    const int lane = tid & 31;
    const int g    = lane >> 2;
    const int t    = lane & 3;
    const int pbase = ((w << 3) | h) << 10;

    const unsigned blm = (lane & 7) + ((lane >> 4) << 3);
    const unsigned blk = ((lane >> 3) & 1) << 4;

    const unsigned khs_b = (unsigned)__cvta_generic_to_shared(khs);
    const unsigned kls_b = (unsigned)__cvta_generic_to_shared(kls);

#pragma unroll
    for (int it = 0; it < 2; ++it) {
        int i4  = tid + it * 128;
        int row = i4 >> 2;
        int c4  = (i4 & 3) << 2;
        unsigned off = (row * 20 + c4) << 2;
        cp16(khs_b + off, g_kh + pbase + i4 * 4);
        cp16(kls_b + off, g_kl + pbase + i4 * 4);
    }
    cp_commit();

    {
        const int mp = tid & 31;
        const int dp = tid >> 5;
        const uint4* v4 = (const uint4*)(g_v16 + pbase);
        uint4 a = v4[(2 * mp) * 4 + dp];
        uint4 b = v4[(2 * mp + 1) * 4 + dp];
        int d0 = dp * 8;
        vts[(d0 + 0) * 36 + mp] = __byte_perm(a.x, b.x, 0x5410);
        vts[(d0 + 1) * 36 + mp] = __byte_perm(a.x, b.x, 0x7632);
        vts[(d0 + 2) * 36 + mp] = __byte_perm(a.y, b.y, 0x5410);
        vts[(d0 + 3) * 36 + mp] = __byte_perm(a.y, b.y, 0x7632);
        vts[(d0 + 4) * 36 + mp] = __byte_perm(a.z, b.z, 0x5410);
        vts[(d0 + 5) * 36 + mp] = __byte_perm(a.z, b.z, 0x7632);
        vts[(d0 + 6) * 36 + mp] = __byte_perm(a.w, b.w, 0x5410);
        vts[(d0 + 7) * 36 + mp] = __byte_perm(a.w, b.w, 0x7632);
    }

    const float sc = g_scale[h];
    const int wy = (w >> 3) & 7, wx = w & 7;
    const int type = ((wy == 7) ? 2 : 0) | ((wx == 7) ? 1 : 0);
    const float* bmr = g_bm + (((type << 3) | h) << 12);
    const int r0 = wt * 16 + g;
    const int r1 = r0 + 8;

    const unsigned* qhp = g_qh + pbase;
    const unsigned* qlp = g_ql + pbase;
    unsigned aqh[2][4], aql[2][4];
#pragma unroll
    for (int ks = 0; ks < 2; ++ks) {
        int bidx = r0 * 16 + ks * 8 + t;
        aqh[ks][0] = qhp[bidx];        aqh[ks][1] = qhp[bidx + 128];
        aqh[ks][2] = qhp[bidx + 4];    aqh[ks][3] = qhp[bidx + 132];
        aql[ks][0] = qlp[bidx];        aql[ks][1] = qlp[bidx + 128];
        aql[ks][2] = qlp[bidx + 4];    aql[ks][3] = qlp[bidx + 132];
    }

    cp_wait<0>();
    __syncthreads();

    float cc[8][4];
#pragma unroll
    for (int nt = 0; nt < 8; ++nt)
#pragma unroll
        for (int q = 0; q < 4; ++q) cc[nt][q] = 0.0f;

#pragma unroll
    for (int ks = 0; ks < 2; ++ks) {
#pragma unroll
        for (int ntp = 0; ntp < 4; ++ntp) {
            unsigned off = (ntp * 16 + blm) * 80 + ks * 32 + blk;
            unsigned rh4[4], rl4[4];
            ldsm4(rh4, khs_b + off);
            ldsm4(rl4, kls_b + off);
            mma16(cc[2 * ntp],     aqh[ks], rh4);
            mma16(cc[2 * ntp],     aql[ks], rh4);
            mma16(cc[2 * ntp],     aqh[ks], rl4);
            mma16(cc[2 * ntp + 1], aqh[ks], rh4 + 2);
            mma16(cc[2 * ntp + 1], aql[ks], rh4 + 2);
            mma16(cc[2 * ntp + 1], aqh[ks], rl4 + 2);
        }
    }

#pragma unroll
    for (int nt = 0; nt < 8; ++nt) {
        float2 b0 = *(const float2*)(bmr + (r0 << 6) + nt * 8 + 2 * t);
        float2 b1 = *(const float2*)(bmr + (r1 << 6) + nt * 8 + 2 * t);
        cc[nt][0] = cc[nt][0] * sc + b0.x;
        cc[nt][1] = cc[nt][1] * sc + b0.y;
        cc[nt][2] = cc[nt][2] * sc + b1.x;
        cc[nt][3] = cc[nt][3] * sc + b1.y;
    }

    float mx0 = -1e30f, mx1 = -1e30f;
#pragma unroll
    for (int nt = 0; nt < 8; ++nt) {
        mx0 = fmaxf(mx0, fmaxf(cc[nt][0], cc[nt][1]));
        mx1 = fmaxf(mx1, fmaxf(cc[nt][2], cc[nt][3]));
    }
    mx0 = fmaxf(mx0, __shfl_xor_sync(0xffffffffu, mx0, 1));
    mx0 = fmaxf(mx0, __shfl_xor_sync(0xffffffffu, mx0, 2));
    mx1 = fmaxf(mx1, __shfl_xor_sync(0xffffffffu, mx1, 1));
    mx1 = fmaxf(mx1, __shfl_xor_sync(0xffffffffu, mx1, 2));

    float s0 = 0.0f, s1 = 0.0f;
#pragma unroll
    for (int nt = 0; nt < 8; ++nt) {
        cc[nt][0] = __expf(cc[nt][0] - mx0);
        cc[nt][1] = __expf(cc[nt][1] - mx0);
        cc[nt][2] = __expf(cc[nt][2] - mx1);
        cc[nt][3] = __expf(cc[nt][3] - mx1);
        s0 += cc[nt][0] + cc[nt][1];
        s1 += cc[nt][2] + cc[nt][3];
    }
    s0 += __shfl_xor_sync(0xffffffffu, s0, 1);
    s0 += __shfl_xor_sync(0xffffffffu, s0, 2);
    s1 += __shfl_xor_sync(0xffffffffu, s1, 1);
    s1 += __shfl_xor_sync(0xffffffffu, s1, 2);
    const float inv0 = 1.0f / s0;
    const float inv1 = 1.0f / s1;

    const unsigned vts_b = (unsigned)__cvta_generic_to_shared(vts);
    float out[4][4];
#pragma unroll
    for (int vt = 0; vt < 4; ++vt)
#pragma unroll
        for (int q = 0; q < 4; ++q) out[vt][q] = 0.0f;

#pragma unroll
    for (int kb = 0; kb < 4; ++kb) {
        unsigned a4[4] = {
            pkh(cc[2 * kb][0],     cc[2 * kb][1]),
            pkh(cc[2 * kb][2],     cc[2 * kb][3]),
            pkh(cc[2 * kb + 1][0], cc[2 * kb + 1][1]),
            pkh(cc[2 * kb + 1][2], cc[2 * kb + 1][3]) };
#pragma unroll
        for (int vtp = 0; vtp < 2; ++vtp) {
            unsigned b4[4];
            ldsm4(b4, vts_b + (vtp * 16 + blm) * 144 + kb * 32 + blk);
            mma16(out[2 * vtp],     a4, b4);
            mma16(out[2 * vtp + 1], a4, b4 + 2);
        }
    }

    const int d0i = (((w << 6) | r0) << 8) + h * 32;
    const int d1i = (((w << 6) | r1) << 8) + h * 32;
    unsigned* ao32 = (unsigned*)g_ao;
#pragma unroll
    for (int vt = 0; vt < 4; ++vt) {
        ao32[(d0i + vt * 8 + 2 * t) >> 1] = pkh(out[vt][0] * inv0, out[vt][1] * inv0);
        ao32[(d1i + vt * 8 + 2 * t) >> 1] = pkh(out[vt][2] * inv1, out[vt][3] * inv1);
    }
}

// ============================================================
// Kernel 3: output projection, M64xN64 warp tile, 128 threads.
// grid 1024: x = bw*2+nh.
// ============================================================
__global__ void __launch_bounds__(128)
swin_proj_kernel(const float* __restrict__ bo, float* __restrict__ out)
{
    extern __shared__ char smem[];
    const unsigned sb = (unsigned)__cvta_generic_to_shared(smem);
    float* bias_s = (float*)(smem + H_BIAS);

    const int bx   = blockIdx.x;
    const int bw   = bx >> 1;
    const int nh   = bx & 1;
    const int tid  = threadIdx.x;
    const int warp = tid >> 5;
    const int lane = tid & 31;
    const int g    = lane >> 2;
    const int t    = lane & 3;
    const int mw   = warp >> 1;
    const int nqw  = warp & 1;

    const unsigned alm = lane & 15;
    const unsigned alk = (lane >> 4) << 4;
    const unsigned blm = (lane & 7) + ((lane >> 4) << 3);
    const unsigned blk = ((lane >> 3) & 1) << 4;

    bias_s[tid] = bo[nh * 128 + tid];
    __syncthreads();

    const int srow = tid >> 3;
    const int sjj  = tid & 7;
    const unsigned short* wh = g_wh + 3 * 65536 + (nh << 15);
    const int abase = bw * 128 * 256;

#define STAGE(c_, st_) do {                                                    \
        unsigned _a = sb + H_BUF + (st_) * QSTG;                               \
        _Pragma("unroll")                                                      \
        for (int _i = 0; _i < 8; ++_i) {                                       \
            int _r = srow + 16 * _i;                                           \
            cp16(_a + _r * 144 + sjj * 16,                                     \
                 g_ao + abase + _r * 256 + (c_) * 64 + sjj * 8);               \
        }                                                                      \
        unsigned _bB = _a + QA_BYTES;                                          \
        _Pragma("unroll")                                                      \
        for (int _i = 0; _i < 8; ++_i) {                                       \
            int _r = srow + 16 * _i;                                           \
            cp16(_bB + _r * 144 + sjj * 16, wh + _r * 256 + (c_) * 64 + sjj * 8); \
        }                                                                      \
        cp_commit();                                                           \
    } while (0)

    STAGE(0, 0); STAGE(1, 1); STAGE(2, 2);

    float acc[4][8][4];
#pragma unroll
    for (int mt = 0; mt < 4; ++mt)
#pragma unroll
        for (int nt = 0; nt < 8; ++nt)
#pragma unroll
            for (int q = 0; q < 4; ++q) acc[mt][nt][q] = 0.0f;

#pragma unroll 1
    for (int c = 0; c < 4; ++c) {
        if      (c == 0) cp_wait<2>();
        else if (c == 1) cp_wait<1>();
        else if (c == 2) cp_wait<1>();
        else             cp_wait<0>();
        __syncthreads();
        if (c == 1) STAGE(3, 0);

        const unsigned sbX = sb + H_BUF + (c % 3) * QSTG;
        const unsigned sbB = sbX + QA_BYTES;
#pragma unroll
        for (int ks = 0; ks < 4; ++ks) {
            unsigned a[4][4];
#pragma unroll
            for (int mt = 0; mt < 4; ++mt)
                ldsm4(a[mt], sbX + (mw * 64 + mt * 16 + alm) * 144 + ks * 32 + alk);
#pragma unroll
            for (int ntp = 0; ntp < 4; ++ntp) {
                unsigned b4[4];
                ldsm4(b4, sbB + (nqw * 64 + ntp * 16 + blm) * 144 + ks * 32 + blk);
#pragma unroll
                for (int mt = 0; mt < 4; ++mt) {
                    mma16(acc[mt][2 * ntp],     a[mt], b4);
                    mma16(acc[mt][2 * ntp + 1], a[mt], b4 + 2);
                }
            }
        }
    }
#undef STAGE

    float2 bb[8];
#pragma unroll
    for (int nt = 0; nt < 8; ++nt)
        bb[nt] = *(float2*)(bias_s + nqw * 64 + nt * 8 + 2 * t);

#pragma unroll
    for (int mt = 0; mt < 4; ++mt)
#pragma unroll
        for (int rh = 0; rh < 2; ++rh)
#pragma unroll
            for (int nt = 0; nt < 8; ++nt) {
                int n   = mw * 64 + mt * 16 + rh * 8 + g;
                int wv  = bw * 2 + (n >> 6);
                int tok = n & 63;
                int b   = wv >> 6, wy = (wv >> 3) & 7, wx = wv & 7;
                int y   = ((wy << 3) + (tok >> 3) + 4) & 63;
                int xc  = ((wx << 3) + (tok & 7) + 4) & 63;
                int col = nh * 128 + nqw * 64 + nt * 8 + 2 * t;
                *(float2*)(out + (((b << 6) | y) << 14) + (xc << 8) + col) =
                    make_float2(acc[mt][nt][rh * 2] + bb[nt].x,
                                acc[mt][nt][rh * 2 + 1] + bb[nt].y);
            }
}

// ============================================================
extern "C" void kernel_launch(void* const* d_in, const int* in_sizes, int n_in,
                              void* d_out, int out_size)
{
    const float* x  = (const float*)d_in[0];
    const float* Wq = (const float*)d_in[1];
    const float* bq = (const float*)d_in[2];
    const float* Wk = (const float*)d_in[3];
    const float* bk = (const float*)d_in[4];
    const float* Wv = (const float*)d_in[5];
    const float* bv = (const float*)d_in[6];
    const float* Wo = (const float*)d_in[7];
    const float* bo = (const float*)d_in[8];
    const float* ls = (const float*)d_in[9];
    const float* w1 = (const float*)d_in[10];
    const float* b1 = (const float*)d_in[11];
    const float* w2 = (const float*)d_in[12];
    float* out = (float*)d_out;

    cudaFuncSetAttribute(swin_qkv_kernel,
                         cudaFuncAttributeMaxDynamicSharedMemorySize, H_SMEM);
    cudaFuncSetAttribute(swin_proj_kernel,
                         cudaFuncAttributeMaxDynamicSharedMemorySize, H_SMEM);

    swin_bias_kernel<<<225, 512>>>(ls, w1, b1, w2);
    swin_bmtab_kernel<<<512, 256>>>();
    swin_cvt_kernel<<<16640, 256>>>(x, Wq, Wk, Wv, Wo);
    swin_qkv_kernel<<<dim3(1024, 3), 128, H_SMEM>>>(bq, bk, bv);
    swin_attn_kernel<<<dim3(NWIN, NHEAD), 128>>>();
    swin_proj_kernel<<<1024, 128, H_SMEM>>>(bo, out);
}